// round 4
// baseline (speedup 1.0000x reference)
#include <cuda_runtime.h>
#include <cstdint>

#define DM   1024
#define DS   256
#define BATCH 8
#define SEQ  2048
#define LCH  16
#define NCH  (SEQ/LCH)      /* 128 */
#define MTOT (BATCH*SEQ)    /* 16384 */

// ---------------- device scratch (no dynamic allocation allowed) -----------
__device__ float g_M [DS*DS];
__device__ float g_T0[DS*DS];
__device__ float g_T1[DS*DS];
__device__ float g_Ad[DS*DS];
__device__ float g_P [7][DS*DS];          // A_d^(16*2^s), s=0..6
__device__ float g_u [MTOT*DS];           // rows = b*SEQ + t
__device__ float g_f [BATCH*NCH*DS];      // chunk-local finals
__device__ float g_g [BATCH*NCH*DS];      // KS ping-pong
__device__ float g_hs[MTOT*DS];           // full hidden states

// ---------------- packed f32x2 helpers -------------------------------------
__device__ __forceinline__ unsigned long long pk2(float a, float b){
    unsigned long long r;
    asm("mov.b64 %0, {%1,%2};" : "=l"(r) : "f"(a), "f"(b));
    return r;
}
__device__ __forceinline__ void unpk2(unsigned long long v, float& a, float& b){
    asm("mov.b64 {%0,%1}, %2;" : "=f"(a), "=f"(b) : "l"(v));
}
__device__ __forceinline__ unsigned long long ffma2(unsigned long long a,
                                                    unsigned long long b,
                                                    unsigned long long c){
    unsigned long long d;
    asm("fma.rn.f32x2 %0, %1, %2, %3;" : "=l"(d) : "l"(a), "l"(b), "l"(c));
    return d;
}

// ---------------- init: M = 0.1*A ; Ad = I + M ; T0 = M --------------------
__global__ void k_init(const float* __restrict__ A){
    int i = blockIdx.x*256 + threadIdx.x;
    float m = 0.1f * A[i];
    g_M[i]  = m;
    g_T0[i] = m;
    int r = i >> 8, c = i & 255;
    g_Ad[i] = m + (r == c ? 1.0f : 0.0f);
}

__device__ __forceinline__ float* selmat(int s){
    switch(s){
        case 0: return g_M;
        case 1: return g_T0;
        case 2: return g_T1;
        case 3: return g_Ad;
        default: return g_P[s-4];
    }
}

// ---------------- 256^3 GEMM, latency-optimized: grid(16,16) x 256 threads --
__global__ void __launch_bounds__(256) k_mm256(int sa, int sb, int sc,
                                               float alpha, int accAd){
    const float* __restrict__ A  = selmat(sa);
    const float* __restrict__ Bm = selmat(sb);
    float*       __restrict__ Cm = selmat(sc);
    __shared__ float As[16][256];     // 16 rows of A
    __shared__ float Bs[256][17];     // 16 cols of B (padded)
    int tid = threadIdx.x;
    int bi = blockIdx.y*16, bj = blockIdx.x*16;

    #pragma unroll
    for(int i = tid; i < 1024; i += 256){           // A tile: 1024 float4
        int r = i >> 6, c4 = i & 63;
        *(float4*)&As[r][c4*4] = *(const float4*)&A[(bi+r)*DS + c4*4];
    }
    #pragma unroll
    for(int i = tid; i < 1024; i += 256){           // B tile: 1024 float4
        int k = i >> 2, c4 = i & 3;
        float4 v = *(const float4*)&Bm[k*DS + bj + c4*4];
        Bs[k][c4*4+0] = v.x; Bs[k][c4*4+1] = v.y;
        Bs[k][c4*4+2] = v.z; Bs[k][c4*4+3] = v.w;
    }
    __syncthreads();

    int r = tid >> 4, c = tid & 15;
    float acc = 0.f;
    #pragma unroll 16
    for(int k = 0; k < 256; k++) acc += As[r][k] * Bs[k][c];

    float v = alpha * acc;
    int idx = (bi + r)*DS + bj + c;
    Cm[idx] = v;
    if(accAd) g_Ad[idx] += v;
}

// ---------------- fold h0 into u[.,0,:]: u0 += h0 @ Ad ----------------------
__global__ void k_h0(const float* __restrict__ h0){
    int j = threadIdx.x;
    for(int b = 0; b < BATCH; b++){
        float acc = 0.f;
        for(int i = 0; i < DS; i++) acc += h0[b*DS+i] * g_Ad[i*DS+j];
        g_u[(size_t)b*SEQ*DS + j] += acc;
    }
}

// ---------------- big SGEMM (f32x2): 128x128x16 tile, 8x8 per thread --------
template<int KDIM, int NDIM, bool EPI>
__global__ void __launch_bounds__(256,2) k_gemm(const float* __restrict__ A,
                                                const float* __restrict__ B,
                                                float* __restrict__ Cout,
                                                const float* __restrict__ X,
                                                const float* __restrict__ Dv){
    const int BK = 16, ASD = 132, BSD = 132;
    __shared__ float As[2][BK*ASD];
    __shared__ float Bs[2][BK*BSD];
    int tid = threadIdx.x;
    int tx = tid & 15, ty = tid >> 4;          // 16 x 16
    int row0 = blockIdx.y * 128;
    int col0 = blockIdx.x * 128;
    int mBase = ty * 8;
    int nBase = tx * 8;

    int a_k4 = tid & 3, a_m = tid >> 2;
    const float* Ap0 = A + (size_t)(row0 + a_m)*KDIM + a_k4*4;
    int b_k = tid >> 4, b_n = (tid & 15)*4;
    const float* Bp0 = B + (size_t)b_k*NDIM + col0 + b_n;

    float4 ra0 = *(const float4*)(Ap0);
    float4 ra1 = *(const float4*)(Ap0 + (size_t)64*KDIM);
    float4 rb0 = *(const float4*)(Bp0);
    float4 rb1 = *(const float4*)(Bp0 + 64);

    #pragma unroll
    for(int jj = 0; jj < 4; jj++){
        As[0][(a_k4*4+jj)*ASD + a_m     ] = ((const float*)&ra0)[jj];
        As[0][(a_k4*4+jj)*ASD + a_m + 64] = ((const float*)&ra1)[jj];
    }
    *(float4*)&Bs[0][b_k*BSD + b_n     ] = rb0;
    *(float4*)&Bs[0][b_k*BSD + b_n + 64] = rb1;
    __syncthreads();

    unsigned long long acc[4][8];
    #pragma unroll
    for(int i = 0; i < 4; i++)
        #pragma unroll
        for(int j = 0; j < 8; j++) acc[i][j] = 0ULL;

    const int NT = KDIM / BK;
    for(int kt = 0; kt < NT; kt++){
        int cur = kt & 1;
        if(kt + 1 < NT){
            const float* Ap = Ap0 + (size_t)(kt+1)*BK;
            ra0 = *(const float4*)(Ap);
            ra1 = *(const float4*)(Ap + (size_t)64*KDIM);
            const float* Bp = Bp0 + (size_t)(kt+1)*BK*NDIM;
            rb0 = *(const float4*)(Bp);
            rb1 = *(const float4*)(Bp + 64);
        }
        #pragma unroll
        for(int k = 0; k < BK; k++){
            const float* asp = &As[cur][k*ASD + mBase];
            ulonglong2 a01 = *(const ulonglong2*)(asp);
            ulonglong2 a23 = *(const ulonglong2*)(asp + 4);
            unsigned long long ar[4] = {a01.x, a01.y, a23.x, a23.y};
            const float* bsp = &Bs[cur][k*BSD + nBase];
            float4 bv0 = *(const float4*)(bsp);
            float4 bv1 = *(const float4*)(bsp + 4);
            unsigned long long bb[8];
            bb[0] = pk2(bv0.x, bv0.x); bb[1] = pk2(bv0.y, bv0.y);
            bb[2] = pk2(bv0.z, bv0.z); bb[3] = pk2(bv0.w, bv0.w);
            bb[4] = pk2(bv1.x, bv1.x); bb[5] = pk2(bv1.y, bv1.y);
            bb[6] = pk2(bv1.z, bv1.z); bb[7] = pk2(bv1.w, bv1.w);
            #pragma unroll
            for(int i = 0; i < 4; i++)
                #pragma unroll
                for(int j = 0; j < 8; j++)
                    acc[i][j] = ffma2(ar[i], bb[j], acc[i][j]);
        }
        if(kt + 1 < NT){
            int nb = cur ^ 1;
            #pragma unroll
            for(int jj = 0; jj < 4; jj++){
                As[nb][(a_k4*4+jj)*ASD + a_m     ] = ((const float*)&ra0)[jj];
                As[nb][(a_k4*4+jj)*ASD + a_m + 64] = ((const float*)&ra1)[jj];
            }
            *(float4*)&Bs[nb][b_k*BSD + b_n     ] = rb0;
            *(float4*)&Bs[nb][b_k*BSD + b_n + 64] = rb1;
            __syncthreads();
        }
    }

    #pragma unroll
    for(int i = 0; i < 4; i++){
        int m0 = row0 + mBase + 2*i;
        float w0[8], w1[8];
        #pragma unroll
        for(int j = 0; j < 8; j++) unpk2(acc[i][j], w0[j], w1[j]);
        int col = col0 + nBase;
        if(EPI){
            float4 d0 = *(const float4*)&Dv[col];
            float4 d1 = *(const float4*)&Dv[col+4];
            float4 xa0 = *(const float4*)&X[(size_t)m0*NDIM + col];
            float4 xa1 = *(const float4*)&X[(size_t)m0*NDIM + col + 4];
            float4 xb0 = *(const float4*)&X[(size_t)(m0+1)*NDIM + col];
            float4 xb1 = *(const float4*)&X[(size_t)(m0+1)*NDIM + col + 4];
            w0[0]+=xa0.x*d0.x; w0[1]+=xa0.y*d0.y; w0[2]+=xa0.z*d0.z; w0[3]+=xa0.w*d0.w;
            w0[4]+=xa1.x*d1.x; w0[5]+=xa1.y*d1.y; w0[6]+=xa1.z*d1.z; w0[7]+=xa1.w*d1.w;
            w1[0]+=xb0.x*d0.x; w1[1]+=xb0.y*d0.y; w1[2]+=xb0.z*d0.z; w1[3]+=xb0.w*d0.w;
            w1[4]+=xb1.x*d1.x; w1[5]+=xb1.y*d1.y; w1[6]+=xb1.z*d1.z; w1[7]+=xb1.w*d1.w;
        }
        *(float4*)&Cout[(size_t)m0*NDIM + col]         = *(float4*)&w0[0];
        *(float4*)&Cout[(size_t)m0*NDIM + col + 4]     = *(float4*)&w0[4];
        *(float4*)&Cout[(size_t)(m0+1)*NDIM + col]     = *(float4*)&w1[0];
        *(float4*)&Cout[(size_t)(m0+1)*NDIM + col + 4] = *(float4*)&w1[4];
    }
}

// ---------------- Phase A: local chunk scans from 0, emit finals ------------
__global__ void __launch_bounds__(256) k_scanA(){
    __shared__ __align__(16) unsigned long long h2[2][DS][4];
    int c = blockIdx.x, j = threadIdx.x;
    #pragma unroll
    for(int p = 0; p < 4; p++) h2[0][j][p] = 0ULL;
    __syncthreads();
    unsigned long long acc[4];
    int cur = 0;
    for(int t = 0; t < LCH; t++){
        int tt = c*LCH + t;
        #pragma unroll
        for(int p = 0; p < 4; p++)
            acc[p] = pk2(g_u[((size_t)(2*p)*SEQ   + tt)*DS + j],
                         g_u[((size_t)(2*p+1)*SEQ + tt)*DS + j]);
        #pragma unroll 8
        for(int i = 0; i < DS; i++){
            float a = g_Ad[i*DS + j];
            unsigned long long aa = pk2(a, a);
            ulonglong2 hA = *(const ulonglong2*)&h2[cur][i][0];
            ulonglong2 hB = *(const ulonglong2*)&h2[cur][i][2];
            acc[0] = ffma2(hA.x, aa, acc[0]);
            acc[1] = ffma2(hA.y, aa, acc[1]);
            acc[2] = ffma2(hB.x, aa, acc[2]);
            acc[3] = ffma2(hB.y, aa, acc[3]);
        }
        #pragma unroll
        for(int p = 0; p < 4; p++) h2[cur^1][j][p] = acc[p];
        __syncthreads();
        cur ^= 1;
    }
    #pragma unroll
    for(int p = 0; p < 4; p++){
        float lo, hi; unpk2(acc[p], lo, hi);
        g_f[((2*p)*NCH   + c)*DS + j] = lo;
        g_f[((2*p+1)*NCH + c)*DS + j] = hi;
    }
}

// ---------------- Phase B: Kogge-Stone over chunk boundaries ----------------
__global__ void __launch_bounds__(256) k_ks(int s){
    int c = blockIdx.x, j = threadIdx.x, d = 1 << s;
    const float* In  = (s & 1) ? g_g : g_f;
    float*       Out = (s & 1) ? g_f : g_g;
    const float* P = g_P[s];
    if(c < d){
        #pragma unroll
        for(int b = 0; b < BATCH; b++)
            Out[(b*NCH + c)*DS + j] = In[(b*NCH + c)*DS + j];
        return;
    }
    __shared__ __align__(16) unsigned long long h2[DS][4];
    #pragma unroll
    for(int p = 0; p < 4; p++)
        h2[j][p] = pk2(In[((2*p)*NCH   + c - d)*DS + j],
                       In[((2*p+1)*NCH + c - d)*DS + j]);
    __syncthreads();
    unsigned long long acc[4];
    #pragma unroll
    for(int p = 0; p < 4; p++)
        acc[p] = pk2(In[((2*p)*NCH   + c)*DS + j],
                     In[((2*p+1)*NCH + c)*DS + j]);
    #pragma unroll 8
    for(int i = 0; i < DS; i++){
        float a = P[i*DS + j];
        unsigned long long aa = pk2(a, a);
        ulonglong2 hA = *(const ulonglong2*)&h2[i][0];
        ulonglong2 hB = *(const ulonglong2*)&h2[i][2];
        acc[0] = ffma2(hA.x, aa, acc[0]);
        acc[1] = ffma2(hA.y, aa, acc[1]);
        acc[2] = ffma2(hB.x, aa, acc[2]);
        acc[3] = ffma2(hB.y, aa, acc[3]);
    }
    #pragma unroll
    for(int p = 0; p < 4; p++){
        float lo, hi; unpk2(acc[p], lo, hi);
        Out[((2*p)*NCH   + c)*DS + j] = lo;
        Out[((2*p+1)*NCH + c)*DS + j] = hi;
    }
}

// ---------------- Phase C: replay chunks from boundary states, emit hs ------
__global__ void __launch_bounds__(256) k_scanC(){
    __shared__ __align__(16) unsigned long long h2[2][DS][4];
    int c = blockIdx.x, j = threadIdx.x;
    if(c == 0){
        #pragma unroll
        for(int p = 0; p < 4; p++) h2[0][j][p] = 0ULL;
    } else {
        #pragma unroll
        for(int p = 0; p < 4; p++)
            h2[0][j][p] = pk2(g_g[((2*p)*NCH   + c - 1)*DS + j],
                              g_g[((2*p+1)*NCH + c - 1)*DS + j]);
    }
    __syncthreads();
    unsigned long long acc[4];
    int cur = 0;
    for(int t = 0; t < LCH; t++){
        int tt = c*LCH + t;
        #pragma unroll
        for(int p = 0; p < 4; p++)
            acc[p] = pk2(g_u[((size_t)(2*p)*SEQ   + tt)*DS + j],
                         g_u[((size_t)(2*p+1)*SEQ + tt)*DS + j]);
        #pragma unroll 8
        for(int i = 0; i < DS; i++){
            float a = g_Ad[i*DS + j];
            unsigned long long aa = pk2(a, a);
            ulonglong2 hA = *(const ulonglong2*)&h2[cur][i][0];
            ulonglong2 hB = *(const ulonglong2*)&h2[cur][i][2];
            acc[0] = ffma2(hA.x, aa, acc[0]);
            acc[1] = ffma2(hA.y, aa, acc[1]);
            acc[2] = ffma2(hB.x, aa, acc[2]);
            acc[3] = ffma2(hB.y, aa, acc[3]);
        }
        #pragma unroll
        for(int p = 0; p < 4; p++){
            h2[cur^1][j][p] = acc[p];
            float lo, hi; unpk2(acc[p], lo, hi);
            g_hs[((size_t)(2*p)*SEQ   + tt)*DS + j] = lo;
            g_hs[((size_t)(2*p+1)*SEQ + tt)*DS + j] = hi;
        }
        __syncthreads();
        cur ^= 1;
    }
}

// ---------------- launch ----------------------------------------------------
extern "C" void kernel_launch(void* const* d_in, const int* in_sizes, int n_in,
                              void* d_out, int out_size){
    const float* x  = (const float*)d_in[0];
    const float* A  = (const float*)d_in[1];
    const float* Bm = (const float*)d_in[2];
    const float* Cm = (const float*)d_in[3];
    const float* Dv = (const float*)d_in[4];
    const float* h0 = (const float*)d_in[5];
    float* y = (float*)d_out;

    void* pu  = nullptr;  cudaGetSymbolAddress(&pu,  g_u);
    void* phs = nullptr;  cudaGetSymbolAddress(&phs, g_hs);

    // u = x @ B  (independent of expm chain)
    k_gemm<DM, DS, false><<<dim3(DS/128, MTOT/128), 256>>>(
        x, Bm, (float*)pu, nullptr, nullptr);

    // expm(0.1A) via Taylor terms 0..6, then powers for the boundary scan
    k_init<<<DS*DS/256, 256>>>(A);
    int src = 1;
    for(int k = 2; k <= 6; k++){
        int dst = (src == 1) ? 2 : 1;
        k_mm256<<<dim3(16,16), 256>>>(src, 0, dst, 1.0f/(float)k, 1);
        src = dst;
    }
    // squarings: T1=Ad^2, T0=Ad^4, T1=Ad^8, P0=Ad^16, P1..P6 by squaring
    k_mm256<<<dim3(16,16), 256>>>(3, 3, 2, 1.0f, 0);
    k_mm256<<<dim3(16,16), 256>>>(2, 2, 1, 1.0f, 0);
    k_mm256<<<dim3(16,16), 256>>>(1, 1, 2, 1.0f, 0);
    k_mm256<<<dim3(16,16), 256>>>(2, 2, 4, 1.0f, 0);
    for(int s = 1; s < 7; s++)
        k_mm256<<<dim3(16,16), 256>>>(3 + s, 3 + s, 4 + s, 1.0f, 0);

    // fold h0 into u (h0 is zero here, but keep it general)
    k_h0<<<1, 256>>>(h0);

    // chunked scan
    k_scanA<<<NCH, 256>>>();
    for(int s = 0; s < 7; s++)
        k_ks<<<NCH, 256>>>(s);
    k_scanC<<<NCH, 256>>>();

    // y = hs @ C + x * D
    k_gemm<DS, DM, true><<<dim3(DM/128, MTOT/128), 256>>>(
        (const float*)phs, Cm, y, x, Dv);
}